// round 1
// baseline (speedup 1.0000x reference)
#include <cuda_runtime.h>
#include <cuda_bf16.h>

// Problem constants
#define BB 2
#define LL 2048
#define DD 1024
#define HH 16
#define dd_ 64
#define MM (BB*LL)          // 4096
#define NC 32               // chunks per sequence (L / 64)
#define CHUNK 64

// ---------------- scratch (device globals, no allocation) ----------------
__device__ float g_Q[MM * DD];
__device__ float g_K[MM * DD];
__device__ float g_V[MM * DD];
__device__ float g_Y[MM * DD];
__device__ float g_S[BB * HH * NC * dd_ * dd_];  // chunk KV states -> exclusive prefix
__device__ float g_Bm[HH * dd_ * dd_];           // symmetric head-mixing matrices

// =====================================================================
// Generic NT GEMM body: C[m][n] = sum_k A[m*1024+k] * B[n*1024+k]
// M=4096, N=1024, K=1024 fixed. 128x128 tile, BK=8, 256 threads, 8x8/thread.
// =====================================================================
__device__ __forceinline__ void gemm_nt_body(const float* __restrict__ A,
                                             const float* __restrict__ B,
                                             float* __restrict__ C) {
    __shared__ float As[8][128];
    __shared__ float Bs[8][128];
    const int tid = threadIdx.x;
    const int bm = blockIdx.y * 128;
    const int bn = blockIdx.x * 128;

    const int lr = tid >> 1;          // 0..127
    const int lc = (tid & 1) << 2;    // 0 or 4
    const float* Ap = A + (size_t)(bm + lr) * 1024 + lc;
    const float* Bp = B + (size_t)(bn + lr) * 1024 + lc;

    const int tr = (tid >> 4) << 3;   // 0..120 step 8
    const int tc = (tid & 15) << 3;

    float acc[8][8];
#pragma unroll
    for (int i = 0; i < 8; i++)
#pragma unroll
        for (int j = 0; j < 8; j++) acc[i][j] = 0.f;

    for (int k0 = 0; k0 < 1024; k0 += 8) {
        float4 av = *(const float4*)(Ap + k0);
        float4 bv = *(const float4*)(Bp + k0);
        __syncthreads();
        As[lc + 0][lr] = av.x; As[lc + 1][lr] = av.y;
        As[lc + 2][lr] = av.z; As[lc + 3][lr] = av.w;
        Bs[lc + 0][lr] = bv.x; Bs[lc + 1][lr] = bv.y;
        Bs[lc + 2][lr] = bv.z; Bs[lc + 3][lr] = bv.w;
        __syncthreads();
#pragma unroll
        for (int kk = 0; kk < 8; kk++) {
            float ar[8], br[8];
            *(float4*)(ar)     = *(const float4*)&As[kk][tr];
            *(float4*)(ar + 4) = *(const float4*)&As[kk][tr + 4];
            *(float4*)(br)     = *(const float4*)&Bs[kk][tc];
            *(float4*)(br + 4) = *(const float4*)&Bs[kk][tc + 4];
#pragma unroll
            for (int i = 0; i < 8; i++)
#pragma unroll
                for (int j = 0; j < 8; j++)
                    acc[i][j] = fmaf(ar[i], br[j], acc[i][j]);
        }
    }
#pragma unroll
    for (int i = 0; i < 8; i++) {
#pragma unroll
        for (int j = 0; j < 8; j += 4) {
            float4 v = make_float4(acc[i][j], acc[i][j+1], acc[i][j+2], acc[i][j+3]);
            *(float4*)&C[(size_t)(bm + tr + i) * 1024 + bn + tc + j] = v;
        }
    }
}

__global__ void __launch_bounds__(256) qkv_gemm_kernel(const float* __restrict__ X,
                                                       const float* __restrict__ Wq,
                                                       const float* __restrict__ Wk,
                                                       const float* __restrict__ Wv) {
    const float* W = (blockIdx.z == 0) ? Wq : (blockIdx.z == 1) ? Wk : Wv;
    float* Cout    = (blockIdx.z == 0) ? g_Q : (blockIdx.z == 1) ? g_K : g_V;
    gemm_nt_body(X, W, Cout);
}

__global__ void __launch_bounds__(256) out_gemm_kernel(const float* __restrict__ Wc,
                                                       float* __restrict__ out) {
    gemm_nt_body(g_Y, Wc, out);
}

// =====================================================================
// Bm[h] = tril(Ltri[h]) @ tril(Ltri[h])^T   (symmetric, 16 x 64 x 64)
// =====================================================================
__global__ void __launch_bounds__(256) bm_kernel(const float* __restrict__ Ltri) {
    const int h = blockIdx.x;
    __shared__ float sL[64 * 64];
    const float* Lp = Ltri + (size_t)h * 4096;
#pragma unroll
    for (int p = 0; p < 4; p++) {
        int e = threadIdx.x * 4 + p * 1024;
        *(float4*)&sL[e] = *(const float4*)&Lp[e];
    }
    __syncthreads();
    for (int p = 0; p < 16; p++) {
        int idx = threadIdx.x + p * 256;
        int e = idx >> 6, d2 = idx & 63;
        int mmax = e < d2 ? e : d2;
        float s = 0.f;
        for (int m = 0; m <= mmax; m++)
            s = fmaf(sL[e * 64 + m], sL[d2 * 64 + m], s);
        g_Bm[(size_t)h * 4096 + idx] = s;
    }
}

// =====================================================================
// Phase 1: per-chunk KV state  S[i][j] = sum_t K[t][i] * V[t][j]
// grid = B*H*NC = 1024 blocks, 256 threads
// =====================================================================
__global__ void __launch_bounds__(256) chunk_state_kernel() {
    const int blk = blockIdx.x;
    const int c  = blk & (NC - 1);
    const int bh = blk >> 5;
    const int b  = bh >> 4;
    const int h  = bh & 15;
    __shared__ float sK[64 * 64];
    __shared__ float sV[64 * 64];
    const size_t rowbase = (size_t)(b * LL + c * CHUNK);
    const float* Kp = g_K + rowbase * 1024 + h * 64;
    const float* Vp = g_V + rowbase * 1024 + h * 64;
    const int tid = threadIdx.x;
#pragma unroll
    for (int p = 0; p < 4; p++) {
        int e = tid * 4 + p * 1024;
        int r = e >> 6, col = e & 63;
        *(float4*)&sK[e] = *(const float4*)&Kp[(size_t)r * 1024 + col];
        *(float4*)&sV[e] = *(const float4*)&Vp[(size_t)r * 1024 + col];
    }
    __syncthreads();
    const int ty = tid >> 4, tx = tid & 15;
    float acc[4][4];
#pragma unroll
    for (int i = 0; i < 4; i++)
#pragma unroll
        for (int j = 0; j < 4; j++) acc[i][j] = 0.f;
    for (int t = 0; t < 64; t++) {
        float4 kv = *(const float4*)&sK[t * 64 + ty * 4];
        float4 vv = *(const float4*)&sV[t * 64 + tx * 4];
        float k[4] = {kv.x, kv.y, kv.z, kv.w};
        float v[4] = {vv.x, vv.y, vv.z, vv.w};
#pragma unroll
        for (int i = 0; i < 4; i++)
#pragma unroll
            for (int j = 0; j < 4; j++)
                acc[i][j] = fmaf(k[i], v[j], acc[i][j]);
    }
    float* Sp = g_S + ((size_t)bh * NC + c) * 4096;
#pragma unroll
    for (int i = 0; i < 4; i++) {
        float4 v = make_float4(acc[i][0], acc[i][1], acc[i][2], acc[i][3]);
        *(float4*)&Sp[(ty * 4 + i) * 64 + tx * 4] = v;
    }
}

// =====================================================================
// Phase 2: exclusive prefix over the NC chunk states, per (b,h).
// grid = 32 blocks, 256 threads; 16 independent chains per thread (MLP).
// =====================================================================
__global__ void __launch_bounds__(256) chunk_scan_kernel() {
    float* Sp = g_S + (size_t)blockIdx.x * NC * 4096;
    const int tid = threadIdx.x;
    float acc[16];
#pragma unroll
    for (int e = 0; e < 16; e++) acc[e] = 0.f;
    for (int c = 0; c < NC; c++) {
        float v[16];
#pragma unroll
        for (int e = 0; e < 16; e++)
            v[e] = Sp[(size_t)c * 4096 + tid + e * 256];
#pragma unroll
        for (int e = 0; e < 16; e++) {
            Sp[(size_t)c * 4096 + tid + e * 256] = acc[e];
            acc[e] += v[e];
        }
    }
}

// =====================================================================
// Phase 3: per-chunk output.
//   Y = Q @ P  +  tril(Q K^T) @ V,   then Y2 = Y @ Bm (Bm symmetric)
// grid = 1024 blocks, 256 threads, dynamic smem = 3 * 64 * 68 floats
// =====================================================================
#define P3 68
extern __shared__ float s3[];

__global__ void __launch_bounds__(256) attn_chunk_kernel() {
    const int blk = blockIdx.x;
    const int c  = blk & (NC - 1);
    const int bh = blk >> 5;
    const int b  = bh >> 4;
    const int h  = bh & 15;

    float* sQ  = s3;                 // [l][i]  pitch 68 (later reused as Y^T [j][l])
    float* sKT = s3 + 64 * P3;       // K transposed [i][t]  (later V as [t][j])
    float* sAT = s3 + 2 * 64 * P3;   // A transposed [t][l]

    const int tid = threadIdx.x;
    const int ty = tid >> 4, tx = tid & 15;
    const size_t rowbase = (size_t)(b * LL + c * CHUNK);
    const float* Qp = g_Q + rowbase * 1024 + h * 64;
    const float* Kp = g_K + rowbase * 1024 + h * 64;
    const float* Vp = g_V + rowbase * 1024 + h * 64;
    const float* Pp = g_S + ((size_t)bh * NC + c) * 4096;   // exclusive prefix state
    const float* Bmp = g_Bm + (size_t)h * 4096;

    // load Q (row layout) and K (transposed)
#pragma unroll
    for (int p = 0; p < 4; p++) {
        int e = tid * 4 + p * 1024;
        int r = e >> 6, col = e & 63;
        float4 q = *(const float4*)&Qp[(size_t)r * 1024 + col];
        *(float4*)&sQ[r * P3 + col] = q;
        float4 kv = *(const float4*)&Kp[(size_t)r * 1024 + col];
        sKT[(col + 0) * P3 + r] = kv.x;
        sKT[(col + 1) * P3 + r] = kv.y;
        sKT[(col + 2) * P3 + r] = kv.z;
        sKT[(col + 3) * P3 + r] = kv.w;
    }
    __syncthreads();

    // fused: acc1 = Q @ P (inter-chunk), acc2 = Q K^T (intra, pre-mask)
    float acc1[4][4], acc2[4][4];
#pragma unroll
    for (int i = 0; i < 4; i++)
#pragma unroll
        for (int j = 0; j < 4; j++) { acc1[i][j] = 0.f; acc2[i][j] = 0.f; }

    for (int i = 0; i < 64; i++) {
        float q[4];
#pragma unroll
        for (int li = 0; li < 4; li++) q[li] = sQ[(ty * 4 + li) * P3 + i];
        float4 pv = __ldg((const float4*)&Pp[i * 64 + tx * 4]);
        float4 kv = *(const float4*)&sKT[i * P3 + tx * 4];
        float pr[4] = {pv.x, pv.y, pv.z, pv.w};
        float kr[4] = {kv.x, kv.y, kv.z, kv.w};
#pragma unroll
        for (int li = 0; li < 4; li++)
#pragma unroll
            for (int j = 0; j < 4; j++) {
                acc1[li][j] = fmaf(q[li], pr[j], acc1[li][j]);
                acc2[li][j] = fmaf(q[li], kr[j], acc2[li][j]);
            }
    }

    // mask + store A^T
#pragma unroll
    for (int li = 0; li < 4; li++)
#pragma unroll
        for (int ti = 0; ti < 4; ti++) {
            int l = ty * 4 + li, t = tx * 4 + ti;
            sAT[t * P3 + l] = (t <= l) ? acc2[li][ti] : 0.f;
        }
    __syncthreads();

    // load V into sKT buffer (row layout [t][j])
#pragma unroll
    for (int p = 0; p < 4; p++) {
        int e = tid * 4 + p * 1024;
        int r = e >> 6, col = e & 63;
        *(float4*)&sKT[r * P3 + col] = *(const float4*)&Vp[(size_t)r * 1024 + col];
    }
    __syncthreads();

    // acc1 += A @ V
    for (int t = 0; t < 64; t++) {
        float4 av = *(const float4*)&sAT[t * P3 + ty * 4];
        float4 vv = *(const float4*)&sKT[t * P3 + tx * 4];
        float a[4] = {av.x, av.y, av.z, av.w};
        float v[4] = {vv.x, vv.y, vv.z, vv.w};
#pragma unroll
        for (int li = 0; li < 4; li++)
#pragma unroll
            for (int j = 0; j < 4; j++)
                acc1[li][j] = fmaf(a[li], v[j], acc1[li][j]);
    }
    __syncthreads();

    // stage Y transposed into sQ buffer: sYT[j][l]
#pragma unroll
    for (int li = 0; li < 4; li++)
#pragma unroll
        for (int ji = 0; ji < 4; ji++)
            sQ[(tx * 4 + ji) * P3 + ty * 4 + li] = acc1[li][ji];
    __syncthreads();

    // acc3 = Y @ Bm  (Bm symmetric so this equals einsum('hed,...d->...e'))
    float acc3[4][4];
#pragma unroll
    for (int i = 0; i < 4; i++)
#pragma unroll
        for (int j = 0; j < 4; j++) acc3[i][j] = 0.f;
    for (int d2 = 0; d2 < 64; d2++) {
        float4 yv = *(const float4*)&sQ[d2 * P3 + ty * 4];
        float4 bm = __ldg((const float4*)&Bmp[d2 * 64 + tx * 4]);
        float y[4] = {yv.x, yv.y, yv.z, yv.w};
        float bb[4] = {bm.x, bm.y, bm.z, bm.w};
#pragma unroll
        for (int li = 0; li < 4; li++)
#pragma unroll
            for (int ei = 0; ei < 4; ei++)
                acc3[li][ei] = fmaf(y[li], bb[ei], acc3[li][ei]);
    }

    float* Yp = g_Y + rowbase * 1024 + h * 64;
#pragma unroll
    for (int li = 0; li < 4; li++) {
        int l = ty * 4 + li;
        float4 v = make_float4(acc3[li][0], acc3[li][1], acc3[li][2], acc3[li][3]);
        *(float4*)&Yp[(size_t)l * 1024 + tx * 4] = v;
    }
}

// =====================================================================
// kernel_launch
// =====================================================================
extern "C" void kernel_launch(void* const* d_in, const int* in_sizes, int n_in,
                              void* d_out, int out_size) {
    const float* X    = (const float*)d_in[0];
    const float* Wq   = (const float*)d_in[1];
    const float* Wk   = (const float*)d_in[2];
    const float* Wv   = (const float*)d_in[3];
    const float* Wc   = (const float*)d_in[4];
    const float* Ltri = (const float*)d_in[5];
    float* out = (float*)d_out;

    const int attn_smem = 3 * 64 * P3 * (int)sizeof(float);  // 52224
    cudaFuncSetAttribute(attn_chunk_kernel,
                         cudaFuncAttributeMaxDynamicSharedMemorySize, attn_smem);

    dim3 gqkv(1024 / 128, MM / 128, 3);
    qkv_gemm_kernel<<<gqkv, 256>>>(X, Wq, Wk, Wv);

    bm_kernel<<<HH, 256>>>(Ltri);
    chunk_state_kernel<<<BB * HH * NC, 256>>>();
    chunk_scan_kernel<<<BB * HH, 256>>>();
    attn_chunk_kernel<<<BB * HH * NC, 256, attn_smem>>>();

    dim3 gout(1024 / 128, MM / 128, 1);
    out_gemm_kernel<<<gout, 256>>>(Wc, out);
}

// round 3
// speedup vs baseline: 2.0949x; 2.0949x over previous
#include <cuda_runtime.h>
#include <cuda_bf16.h>

typedef unsigned int u32;

// Problem constants
#define BB 2
#define LL 2048
#define DD 1024
#define HH 16
#define MM (BB*LL)          // 4096
#define NC 32               // chunks per sequence
#define CHUNK 64

// ---------------- scratch (device globals, no allocation) ----------------
__device__ float g_Q[MM * DD];
__device__ float g_K[MM * DD];
__device__ float g_V[MM * DD];
__device__ float g_Y[MM * DD];
__device__ float g_S[BB * HH * NC * 64 * 64];
__device__ float g_Bm[HH * 64 * 64];

extern __shared__ unsigned char dynsmem[];

// =====================================================================
// helpers
// =====================================================================
__device__ __forceinline__ u32 smem_u32(const void* p) {
    u32 a;
    asm("{ .reg .u64 t; cvta.to.shared.u64 t, %1; cvt.u32.u64 %0, t; }"
        : "=r"(a) : "l"(p));
    return a;
}

__device__ __forceinline__ void ldsm4(u32 r[4], u32 addr) {
    asm volatile("ldmatrix.sync.aligned.m8n8.x4.shared.b16 {%0,%1,%2,%3}, [%4];"
                 : "=r"(r[0]), "=r"(r[1]), "=r"(r[2]), "=r"(r[3]) : "r"(addr));
}

__device__ __forceinline__ void mma_bf16(float c[4], const u32 a[4], u32 b0, u32 b1) {
    asm volatile(
        "mma.sync.aligned.m16n8k16.row.col.f32.bf16.bf16.f32 "
        "{%0,%1,%2,%3}, {%4,%5,%6,%7}, {%8,%9}, {%0,%1,%2,%3};"
        : "+f"(c[0]), "+f"(c[1]), "+f"(c[2]), "+f"(c[3])
        : "r"(a[0]), "r"(a[1]), "r"(a[2]), "r"(a[3]), "r"(b0), "r"(b1));
}

// pack two floats to bf16x2 [bf(hi_val)|bf(lo_val)], return residuals
__device__ __forceinline__ u32 pack_hi(float v0, float v1) {
    u32 p;
    asm("cvt.rn.bf16x2.f32 %0, %1, %2;" : "=r"(p) : "f"(v1), "f"(v0));
    return p;   // low 16 = bf(v0), high 16 = bf(v1)
}

// =====================================================================
// Tensor-core GEMM via mma.sync (bf16 3-term split, fp32 accum)
// C[m][n] = sum_k A[m*1024+k] * B[n*1024+k];  M=4096 (by grid), N=1024, K=1024
// CTA 128x128, BK=32, 8 warps (2x4 -> 64x32 warp tiles), double buffer.
// SMEM per stage: Ah,Al,Bh,Bl each 128 rows x 40 halves (80B pitch) = 10240B.
// =====================================================================
#define ROWP 40                       // padded row pitch in halves
#define STG  (4 * 128 * ROWP * 2)     // 40960 bytes per stage
#define GEMM_SMEM (2 * STG)

__device__ __forceinline__ void stage_quarter(unsigned char* dst_h,
                                              unsigned char* dst_l,
                                              const float* __restrict__ g,
                                              int lrow, int lcg) {
#pragma unroll
    for (int i = 0; i < 4; i++) {
        int row = lrow + i * 32;
        float4 v = *(const float4*)(g + (size_t)i * 32 * 1024);
        u32 p0 = pack_hi(v.x, v.y);
        u32 p1 = pack_hi(v.z, v.w);
        float r0 = v.x - __uint_as_float(p0 << 16);
        float r1 = v.y - __uint_as_float(p0 & 0xFFFF0000u);
        float r2 = v.z - __uint_as_float(p1 << 16);
        float r3 = v.w - __uint_as_float(p1 & 0xFFFF0000u);
        u32 q0 = pack_hi(r0, r1);
        u32 q1 = pack_hi(r2, r3);
        u32 off = (u32)(row * (ROWP * 2) + lcg * 8);
        *(uint2*)(dst_h + off) = make_uint2(p0, p1);
        *(uint2*)(dst_l + off) = make_uint2(q0, q1);
    }
}

__device__ __forceinline__ void gemm_tc_body(const float* __restrict__ A,
                                             const float* __restrict__ Bmat,
                                             float* __restrict__ C) {
    const int tid = threadIdx.x;
    const int lane = tid & 31, wid = tid >> 5;
    const int bm = blockIdx.y * 128, bn = blockIdx.x * 128;
    const int mW = (wid >> 2) * 64, nW = (wid & 3) * 32;
    u32 sb = smem_u32(dynsmem);

    float acc[4][4][4];
#pragma unroll
    for (int mi = 0; mi < 4; mi++)
#pragma unroll
        for (int ni = 0; ni < 4; ni++)
#pragma unroll
            for (int r = 0; r < 4; r++) acc[mi][ni][r] = 0.f;

    const int lrow = tid >> 3;       // 0..31
    const int lcg  = tid & 7;        // 0..7
    const float* Ag = A    + (size_t)(bm + lrow) * 1024 + lcg * 4;
    const float* Bg = Bmat + (size_t)(bn + lrow) * 1024 + lcg * 4;

    // ldmatrix source addresses (fixed per lane; add stage/k offsets later)
    const u32 aAddrBase = sb + (u32)((mW + (lane & 15)) * ROWP + (lane >> 4) * 8) * 2;
    const u32 bAddr0Base = sb + 20480u + (u32)((nW + (lane & 15)) * ROWP + (lane >> 4) * 8) * 2;
    const u32 bAddr1Base = bAddr0Base + 16u * ROWP * 2u;

    // prologue: stage k-tile 0 into buffer 0
    stage_quarter(dynsmem,          dynsmem + 10240, Ag, lrow, lcg);
    stage_quarter(dynsmem + 20480,  dynsmem + 30720, Bg, lrow, lcg);
    __syncthreads();

    for (int kt = 0; kt < 32; kt++) {
        const int s = kt & 1;
        const u32 soff = (u32)s * STG;

        // prefetch next k-tile into registers
        float4 av[4], bv[4];
        if (kt < 31) {
            const float* Agn = Ag + (kt + 1) * 32;
            const float* Bgn = Bg + (kt + 1) * 32;
#pragma unroll
            for (int i = 0; i < 4; i++) {
                av[i] = *(const float4*)(Agn + (size_t)i * 32 * 1024);
                bv[i] = *(const float4*)(Bgn + (size_t)i * 32 * 1024);
            }
        }

        // compute on buffer s
#pragma unroll
        for (int ks = 0; ks < 2; ks++) {
            const u32 ko = (u32)(ks * 16 * 2);
            u32 Ah[4][4], Al[4][4];
#pragma unroll
            for (int mi = 0; mi < 4; mi++) {
                u32 ad = aAddrBase + soff + (u32)(mi * 16 * ROWP * 2) + ko;
                ldsm4(Ah[mi], ad);
                ldsm4(Al[mi], ad + 10240u);
            }
            u32 Bh0[4], Bh1[4], Bl0[4], Bl1[4];
            {
                u32 b0 = bAddr0Base + soff + ko;
                u32 b1 = bAddr1Base + soff + ko;
                ldsm4(Bh0, b0); ldsm4(Bl0, b0 + 10240u);
                ldsm4(Bh1, b1); ldsm4(Bl1, b1 + 10240u);
            }
#pragma unroll
            for (int mi = 0; mi < 4; mi++) {
#pragma unroll
                for (int ni = 0; ni < 4; ni++) {
                    u32 bh0 = (ni < 2) ? Bh0[ni]     : Bh1[ni - 2];
                    u32 bh1 = (ni < 2) ? Bh0[ni + 2] : Bh1[ni];
                    u32 bl0 = (ni < 2) ? Bl0[ni]     : Bl1[ni - 2];
                    u32 bl1 = (ni < 2) ? Bl0[ni + 2] : Bl1[ni];
                    mma_bf16(acc[mi][ni], Ah[mi], bh0, bh1);
                    mma_bf16(acc[mi][ni], Ah[mi], bl0, bl1);
                    mma_bf16(acc[mi][ni], Al[mi], bh0, bh1);
                }
            }
        }

        // write prefetched tile to the other buffer
        if (kt < 31) {
            unsigned char* dst = dynsmem + ((kt + 1) & 1) * STG;
            const u32 off = (u32)(lrow * (ROWP * 2) + lcg * 8);
#pragma unroll
            for (int i = 0; i < 4; i++) {
                u32 roff = off + (u32)(i * 32 * ROWP * 2);
                u32 p0 = pack_hi(av[i].x, av[i].y);
                u32 p1 = pack_hi(av[i].z, av[i].w);
                float r0 = av[i].x - __uint_as_float(p0 << 16);
                float r1 = av[i].y - __uint_as_float(p0 & 0xFFFF0000u);
                float r2 = av[i].z - __uint_as_float(p1 << 16);
                float r3 = av[i].w - __uint_as_float(p1 & 0xFFFF0000u);
                *(uint2*)(dst + roff) = make_uint2(p0, p1);
                *(uint2*)(dst + 10240 + roff) = make_uint2(pack_hi(r0, r1), pack_hi(r2, r3));
                p0 = pack_hi(bv[i].x, bv[i].y);
                p1 = pack_hi(bv[i].z, bv[i].w);
                r0 = bv[i].x - __uint_as_float(p0 << 16);
                r1 = bv[i].y - __uint_as_float(p0 & 0xFFFF0000u);
                r2 = bv[i].z - __uint_as_float(p1 << 16);
                r3 = bv[i].w - __uint_as_float(p1 & 0xFFFF0000u);
                *(uint2*)(dst + 20480 + roff) = make_uint2(p0, p1);
                *(uint2*)(dst + 30720 + roff) = make_uint2(pack_hi(r0, r1), pack_hi(r2, r3));
            }
        }
        __syncthreads();
    }

    // epilogue
#pragma unroll
    for (int mi = 0; mi < 4; mi++) {
#pragma unroll
        for (int ni = 0; ni < 4; ni++) {
            int row = bm + mW + mi * 16 + (lane >> 2);
            int col = bn + nW + ni * 8 + (lane & 3) * 2;
            *(float2*)&C[(size_t)row * 1024 + col] =
                make_float2(acc[mi][ni][0], acc[mi][ni][1]);
            *(float2*)&C[(size_t)(row + 8) * 1024 + col] =
                make_float2(acc[mi][ni][2], acc[mi][ni][3]);
        }
    }
}

__global__ void __launch_bounds__(256) qkv_gemm_kernel(const float* __restrict__ X,
                                                       const float* __restrict__ Wq,
                                                       const float* __restrict__ Wk,
                                                       const float* __restrict__ Wv) {
    const float* W = (blockIdx.z == 0) ? Wq : (blockIdx.z == 1) ? Wk : Wv;
    float* Cout    = (blockIdx.z == 0) ? g_Q : (blockIdx.z == 1) ? g_K : g_V;
    gemm_tc_body(X, W, Cout);
}

__global__ void __launch_bounds__(256) out_gemm_kernel(const float* __restrict__ Wc,
                                                       float* __restrict__ out) {
    gemm_tc_body(g_Y, Wc, out);
}

// =====================================================================
// Bm[h] = tril(Ltri[h]) @ tril(Ltri[h])^T
// =====================================================================
__global__ void __launch_bounds__(256) bm_kernel(const float* __restrict__ Ltri) {
    const int h = blockIdx.x;
    __shared__ float sL[64 * 64];
    const float* Lp = Ltri + (size_t)h * 4096;
#pragma unroll
    for (int p = 0; p < 4; p++) {
        int e = threadIdx.x * 4 + p * 1024;
        *(float4*)&sL[e] = *(const float4*)&Lp[e];
    }
    __syncthreads();
    for (int p = 0; p < 16; p++) {
        int idx = threadIdx.x + p * 256;
        int e = idx >> 6, d2 = idx & 63;
        int mmax = e < d2 ? e : d2;
        float s = 0.f;
        for (int m = 0; m <= mmax; m++)
            s = fmaf(sL[e * 64 + m], sL[d2 * 64 + m], s);
        g_Bm[(size_t)h * 4096 + idx] = s;
    }
}

// =====================================================================
// Phase 1: per-chunk KV state  S[i][j] = sum_t K[t][i] * V[t][j]
// =====================================================================
__global__ void __launch_bounds__(256) chunk_state_kernel() {
    const int blk = blockIdx.x;
    const int c  = blk & (NC - 1);
    const int bh = blk >> 5;
    const int b  = bh >> 4;
    const int h  = bh & 15;
    __shared__ float sK[64 * 64];
    __shared__ float sV[64 * 64];
    const size_t rowbase = (size_t)(b * LL + c * CHUNK);
    const float* Kp = g_K + rowbase * 1024 + h * 64;
    const float* Vp = g_V + rowbase * 1024 + h * 64;
    const int tid = threadIdx.x;
#pragma unroll
    for (int p = 0; p < 4; p++) {
        int e = tid * 4 + p * 1024;
        int r = e >> 6, col = e & 63;
        *(float4*)&sK[e] = *(const float4*)&Kp[(size_t)r * 1024 + col];
        *(float4*)&sV[e] = *(const float4*)&Vp[(size_t)r * 1024 + col];
    }
    __syncthreads();
    const int ty = tid >> 4, tx = tid & 15;
    float acc[4][4];
#pragma unroll
    for (int i = 0; i < 4; i++)
#pragma unroll
        for (int j = 0; j < 4; j++) acc[i][j] = 0.f;
    for (int t = 0; t < 64; t++) {
        float4 kv = *(const float4*)&sK[t * 64 + ty * 4];
        float4 vv = *(const float4*)&sV[t * 64 + tx * 4];
        float k[4] = {kv.x, kv.y, kv.z, kv.w};
        float v[4] = {vv.x, vv.y, vv.z, vv.w};
#pragma unroll
        for (int i = 0; i < 4; i++)
#pragma unroll
            for (int j = 0; j < 4; j++)
                acc[i][j] = fmaf(k[i], v[j], acc[i][j]);
    }
    float* Sp = g_S + ((size_t)bh * NC + c) * 4096;
#pragma unroll
    for (int i = 0; i < 4; i++) {
        float4 v = make_float4(acc[i][0], acc[i][1], acc[i][2], acc[i][3]);
        *(float4*)&Sp[(ty * 4 + i) * 64 + tx * 4] = v;
    }
}

// =====================================================================
// Phase 2: exclusive prefix over NC chunk states.
// One thread per (bh, element) chain: 131072 chains, fully parallel.
// =====================================================================
__global__ void __launch_bounds__(256) chunk_scan_kernel() {
    int idx = blockIdx.x * 256 + threadIdx.x;          // 0..131071
    float* p = g_S + (size_t)(idx >> 12) * (NC * 4096) + (idx & 4095);
    float acc = 0.f;
#pragma unroll
    for (int c = 0; c < NC; c++) {
        float v = p[(size_t)c * 4096];
        p[(size_t)c * 4096] = acc;
        acc += v;
    }
}

// =====================================================================
// Phase 3: per-chunk output.
//   Y = Q @ P  +  tril(Q K^T) @ V,   then Y2 = Y @ Bm
// =====================================================================
#define P3 68

__global__ void __launch_bounds__(256) attn_chunk_kernel() {
    float* s3 = (float*)dynsmem;
    const int blk = blockIdx.x;
    const int c  = blk & (NC - 1);
    const int bh = blk >> 5;
    const int b  = bh >> 4;
    const int h  = bh & 15;

    float* sQ  = s3;
    float* sKT = s3 + 64 * P3;
    float* sAT = s3 + 2 * 64 * P3;

    const int tid = threadIdx.x;
    const int ty = tid >> 4, tx = tid & 15;
    const size_t rowbase = (size_t)(b * LL + c * CHUNK);
    const float* Qp = g_Q + rowbase * 1024 + h * 64;
    const float* Kp = g_K + rowbase * 1024 + h * 64;
    const float* Vp = g_V + rowbase * 1024 + h * 64;
    const float* Pp = g_S + ((size_t)bh * NC + c) * 4096;
    const float* Bmp = g_Bm + (size_t)h * 4096;

#pragma unroll
    for (int p = 0; p < 4; p++) {
        int e = tid * 4 + p * 1024;
        int r = e >> 6, col = e & 63;
        float4 q = *(const float4*)&Qp[(size_t)r * 1024 + col];
        *(float4*)&sQ[r * P3 + col] = q;
        float4 kv = *(const float4*)&Kp[(size_t)r * 1024 + col];
        sKT[(col + 0) * P3 + r] = kv.x;
        sKT[(col + 1) * P3 + r] = kv.y;
        sKT[(col + 2) * P3 + r] = kv.z;
        sKT[(col + 3) * P3 + r] = kv.w;
    }
    __syncthreads();

    float acc1[4][4], acc2[4][4];
#pragma unroll
    for (int i = 0; i < 4; i++)
#pragma unroll
        for (int j = 0; j < 4; j++) { acc1[i][j] = 0.f; acc2[i][j] = 0.f; }

    for (int i = 0; i < 64; i++) {
        float q[4];
#pragma unroll
        for (int li = 0; li < 4; li++) q[li] = sQ[(ty * 4 + li) * P3 + i];
        float4 pv = __ldg((const float4*)&Pp[i * 64 + tx * 4]);
        float4 kv = *(const float4*)&sKT[i * P3 + tx * 4];
        float pr[4] = {pv.x, pv.y, pv.z, pv.w};
        float kr[4] = {kv.x, kv.y, kv.z, kv.w};
#pragma unroll
        for (int li = 0; li < 4; li++)
#pragma unroll
            for (int j = 0; j < 4; j++) {
                acc1[li][j] = fmaf(q[li], pr[j], acc1[li][j]);
                acc2[li][j] = fmaf(q[li], kr[j], acc2[li][j]);
            }
    }

#pragma unroll
    for (int li = 0; li < 4; li++)
#pragma unroll
        for (int ti = 0; ti < 4; ti++) {
            int l = ty * 4 + li, t = tx * 4 + ti;
            sAT[t * P3 + l] = (t <= l) ? acc2[li][ti] : 0.f;
        }
    __syncthreads();

#pragma unroll
    for (int p = 0; p < 4; p++) {
        int e = tid * 4 + p * 1024;
        int r = e >> 6, col = e & 63;
        *(float4*)&sKT[r * P3 + col] = *(const float4*)&Vp[(size_t)r * 1024 + col];
    }
    __syncthreads();

    for (int t = 0; t < 64; t++) {
        float4 av = *(const float4*)&sAT[t * P3 + ty * 4];
        float4 vv = *(const float4*)&sKT[t * P3 + tx * 4];
        float a[4] = {av.x, av.y, av.z, av.w};
        float v[4] = {vv.x, vv.y, vv.z, vv.w};
#pragma unroll
        for (int li = 0; li < 4; li++)
#pragma unroll
            for (int j = 0; j < 4; j++)
                acc1[li][j] = fmaf(a[li], v[j], acc1[li][j]);
    }
    __syncthreads();

#pragma unroll
    for (int li = 0; li < 4; li++)
#pragma unroll
        for (int ji = 0; ji < 4; ji++)
            sQ[(tx * 4 + ji) * P3 + ty * 4 + li] = acc1[li][ji];
    __syncthreads();

    float acc3[4][4];
#pragma unroll
    for (int i = 0; i < 4; i++)
#pragma unroll
        for (int j = 0; j < 4; j++) acc3[i][j] = 0.f;
    for (int d2 = 0; d2 < 64; d2++) {
        float4 yv = *(const float4*)&sQ[d2 * P3 + ty * 4];
        float4 bm = __ldg((const float4*)&Bmp[d2 * 64 + tx * 4]);
        float y[4] = {yv.x, yv.y, yv.z, yv.w};
        float bb[4] = {bm.x, bm.y, bm.z, bm.w};
#pragma unroll
        for (int li = 0; li < 4; li++)
#pragma unroll
            for (int ei = 0; ei < 4; ei++)
                acc3[li][ei] = fmaf(y[li], bb[ei], acc3[li][ei]);
    }

    float* Yp = g_Y + rowbase * 1024 + h * 64;
#pragma unroll
    for (int li = 0; li < 4; li++) {
        int l = ty * 4 + li;
        float4 v = make_float4(acc3[li][0], acc3[li][1], acc3[li][2], acc3[li][3]);
        *(float4*)&Yp[(size_t)l * 1024 + tx * 4] = v;
    }
}

// =====================================================================
// kernel_launch
// =====================================================================
extern "C" void kernel_launch(void* const* d_in, const int* in_sizes, int n_in,
                              void* d_out, int out_size) {
    const float* X    = (const float*)d_in[0];
    const float* Wq   = (const float*)d_in[1];
    const float* Wk   = (const float*)d_in[2];
    const float* Wv   = (const float*)d_in[3];
    const float* Wc   = (const float*)d_in[4];
    const float* Ltri = (const float*)d_in[5];
    float* out = (float*)d_out;

    const int attn_smem = 3 * 64 * P3 * (int)sizeof(float);
    cudaFuncSetAttribute(attn_chunk_kernel,
                         cudaFuncAttributeMaxDynamicSharedMemorySize, attn_smem);
    cudaFuncSetAttribute(qkv_gemm_kernel,
                         cudaFuncAttributeMaxDynamicSharedMemorySize, GEMM_SMEM);
    cudaFuncSetAttribute(out_gemm_kernel,
                         cudaFuncAttributeMaxDynamicSharedMemorySize, GEMM_SMEM);

    dim3 gqkv(DD / 128, MM / 128, 3);
    qkv_gemm_kernel<<<gqkv, 256, GEMM_SMEM>>>(X, Wq, Wk, Wv);

    bm_kernel<<<HH, 256>>>(Ltri);
    chunk_state_kernel<<<BB * HH * NC, 256>>>();
    chunk_scan_kernel<<<512, 256>>>();
    attn_chunk_kernel<<<BB * HH * NC, 256, attn_smem>>>();

    dim3 gout(DD / 128, MM / 128, 1);
    out_gemm_kernel<<<gout, 256, GEMM_SMEM>>>(Wc, out);
}